// round 16
// baseline (speedup 1.0000x reference)
#include <cuda_runtime.h>
#include <cuda_bf16.h>
#include <math.h>
#include <stdint.h>

#define BDIM 1024
#define PDIM 64
#define CDIM 512

// ---------------------------------------------------------------------------
// Scratch (device globals; no allocations allowed)
// ---------------------------------------------------------------------------
__device__ __align__(128) __nv_bfloat16 g_xh[(size_t)CDIM * BDIM * PDIM];
__device__ __align__(128) __nv_bfloat16 g_xl[(size_t)CDIM * BDIM * PDIM];
__device__ __align__(128) float         g_res[(size_t)CDIM * BDIM * PDIM];
__device__ __align__(128) __nv_bfloat16 g_w1h[(size_t)CDIM * PDIM * PDIM];
__device__ __align__(128) __nv_bfloat16 g_w1l[(size_t)CDIM * PDIM * PDIM];
__device__ __align__(128) __nv_bfloat16 g_w2h[(size_t)CDIM * PDIM * PDIM];
__device__ __align__(128) __nv_bfloat16 g_w2l[(size_t)CDIM * PDIM * PDIM];

// ---------------------------------------------------------------------------
// mma.sync / ldmatrix helpers (baseline PTX — compiles for compute_103)
// ---------------------------------------------------------------------------
__device__ __forceinline__ uint32_t smem_u32(const void* p) {
    uint32_t a;
    asm("{ .reg .u64 t; cvta.to.shared.u64 t, %1; cvt.u32.u64 %0, t; }" : "=r"(a) : "l"(p));
    return a;
}

#define LDM_X4(r, addr)                                                         \
    asm volatile("ldmatrix.sync.aligned.m8n8.x4.shared.b16 {%0,%1,%2,%3}, [%4];"\
        : "=r"((r)[0]), "=r"((r)[1]), "=r"((r)[2]), "=r"((r)[3]) : "r"(addr))

#define LDM_X2(r, addr)                                                         \
    asm volatile("ldmatrix.sync.aligned.m8n8.x2.shared.b16 {%0,%1}, [%2];"      \
        : "=r"((r)[0]), "=r"((r)[1]) : "r"(addr))

#define MMA_BF16(c, a, b)                                                       \
    asm volatile("mma.sync.aligned.m16n8k16.row.col.f32.bf16.bf16.f32 "         \
        "{%0,%1,%2,%3}, {%4,%5,%6,%7}, {%8,%9}, {%0,%1,%2,%3};"                 \
        : "+f"((c)[0]), "+f"((c)[1]), "+f"((c)[2]), "+f"((c)[3])                \
        : "r"((a)[0]), "r"((a)[1]), "r"((a)[2]), "r"((a)[3]),                   \
          "r"((b)[0]), "r"((b)[1]))

__device__ __forceinline__ float bf16lo(uint32_t u) { return __uint_as_float(u << 16); }
__device__ __forceinline__ float bf16hi(uint32_t u) { return __uint_as_float(u & 0xFFFF0000u); }

// ---------------------------------------------------------------------------
// Kernel 1: split W -> bf16 hi/lo, 8 elements per thread (vectorized)
// ---------------------------------------------------------------------------
__global__ void __launch_bounds__(256)
wsplit_kernel(const float* __restrict__ W1, const float* __restrict__ W2,
              __nv_bfloat16* __restrict__ w1h, __nv_bfloat16* __restrict__ w1l,
              __nv_bfloat16* __restrict__ w2h, __nv_bfloat16* __restrict__ w2l)
{
    size_t i8 = ((size_t)blockIdx.x * 256 + threadIdx.x) * 8;
#pragma unroll
    for (int w = 0; w < 2; w++) {
        const float* src = w ? W2 : W1;
        __nv_bfloat16* dh = w ? w2h : w1h;
        __nv_bfloat16* dl = w ? w2l : w1l;
        float v[8];
        *(float4*)(v)     = *(const float4*)(src + i8);
        *(float4*)(v + 4) = *(const float4*)(src + i8 + 4);
        __nv_bfloat16 hv[8], lv[8];
#pragma unroll
        for (int j = 0; j < 8; j++) {
            hv[j] = __float2bfloat16(v[j]);
            lv[j] = __float2bfloat16(v[j] - __bfloat162float(hv[j]));
        }
        *(uint4*)(dh + i8) = *(uint4*)hv;
        *(uint4*)(dl + i8) = *(uint4*)lv;
    }
}

// ---------------------------------------------------------------------------
// Kernel 2: transpose + split  x[b,p,c] -> xh/xl[c,b,p] (bf16).
// ---------------------------------------------------------------------------
__global__ void __launch_bounds__(256)
xsplit_kernel(const float* __restrict__ x,
              __nv_bfloat16* __restrict__ xh, __nv_bfloat16* __restrict__ xl)
{
    __shared__ float sm[32][261];
    const int b0 = blockIdx.y * 4;
    const int c0 = blockIdx.x * 32;

    for (int i = threadIdx.x; i < 4 * 64 * 32; i += 256) {
        int cc = i & 31, p = (i >> 5) & 63, b = i >> 11;
        sm[cc][b * 64 + p] = x[((size_t)(b0 + b) * PDIM + p) * CDIM + c0 + cc];
    }
    __syncthreads();

    const int cc = threadIdx.x >> 3;
    const int p0 = (threadIdx.x & 7) * 8;
#pragma unroll
    for (int b = 0; b < 4; b++) {
        __nv_bfloat16 hv[8], lv[8];
#pragma unroll
        for (int i = 0; i < 8; i++) {
            float v = sm[cc][b * 64 + p0 + i];
            hv[i] = __float2bfloat16(v);
            lv[i] = __float2bfloat16(v - __bfloat162float(hv[i]));
        }
        size_t base = ((size_t)(c0 + cc) * BDIM + b0 + b) * PDIM + p0;
        *(uint4*)(xh + base) = *(uint4*)hv;
        *(uint4*)(xl + base) = *(uint4*)lv;
    }
}

// ---------------------------------------------------------------------------
// Kernel 3: FUSED double GEMM per (c, 128-batch tile) [R7 scheme verbatim]
// ---------------------------------------------------------------------------
__global__ void __launch_bounds__(256)
fused_gemm_kernel(const __nv_bfloat16* __restrict__ Ah_g, const __nv_bfloat16* __restrict__ Al_g,
                  const __nv_bfloat16* __restrict__ W1h_g, const __nv_bfloat16* __restrict__ W1l_g,
                  const __nv_bfloat16* __restrict__ W2h_g, const __nv_bfloat16* __restrict__ W2l_g,
                  const float* __restrict__ b1, const float* __restrict__ b2,
                  float* __restrict__ outF)
{
    extern __shared__ __align__(16) char smem[];
    const uint32_t AH = 0, AL = 18432;
    const uint32_t B1H = 36864, B1L = 46080;
    const uint32_t B2H = 55296, B2L = 64512;
    const uint32_t BIAS1 = 73728, BIAS2 = 73984;

    const int tid  = threadIdx.x;
    const int warp = tid >> 5;
    const int lane = tid & 31;
    const int b0   = blockIdx.x * 128;
    const int c    = blockIdx.y;

    {
        const uint4* sAh = (const uint4*)(Ah_g + ((size_t)c * BDIM + b0) * PDIM);
        const uint4* sAl = (const uint4*)(Al_g + ((size_t)c * BDIM + b0) * PDIM);
        for (int i = tid; i < 1024; i += 256) {
            int row = i >> 3, ch = i & 7;
            *(uint4*)(smem + AH + row * 144 + ch * 16) = sAh[i];
            *(uint4*)(smem + AL + row * 144 + ch * 16) = sAl[i];
        }
        const uint4* s1h = (const uint4*)(W1h_g + (size_t)c * PDIM * PDIM);
        const uint4* s1l = (const uint4*)(W1l_g + (size_t)c * PDIM * PDIM);
        const uint4* s2h = (const uint4*)(W2h_g + (size_t)c * PDIM * PDIM);
        const uint4* s2l = (const uint4*)(W2l_g + (size_t)c * PDIM * PDIM);
        for (int i = tid; i < 512; i += 256) {
            int row = i >> 3, ch = i & 7;
            *(uint4*)(smem + B1H + row * 144 + ch * 16) = s1h[i];
            *(uint4*)(smem + B1L + row * 144 + ch * 16) = s1l[i];
            *(uint4*)(smem + B2H + row * 144 + ch * 16) = s2h[i];
            *(uint4*)(smem + B2L + row * 144 + ch * 16) = s2l[i];
        }
        if (tid < 64) {
            ((float*)(smem + BIAS1))[tid] = b1[(size_t)c * PDIM + tid];
            ((float*)(smem + BIAS2))[tid] = b2[(size_t)c * PDIM + tid];
        }
    }
    __syncthreads();

    const uint32_t sb = smem_u32(smem);
    const uint32_t aAdrH = sb + AH + (uint32_t)(warp * 16 + (lane & 15)) * 144 + (uint32_t)(lane >> 4) * 16;
    const uint32_t aAdrL = aAdrH + (AL - AH);
    const uint32_t bBase = sb + (uint32_t)(lane & 7) * 144 + (uint32_t)((lane >> 3) & 1) * 16;

    const int gid = lane >> 2, tq = lane & 3;
    const int r0 = warp * 16 + gid, r1 = r0 + 8;

    // ================= GEMM 1 =================
    float acc[8][4] = {};
#pragma unroll
    for (int kc = 0; kc < 4; kc++) {
        uint32_t ah[4], al[4];
        LDM_X4(ah, aAdrH + kc * 32);
        LDM_X4(al, aAdrL + kc * 32);
#pragma unroll
        for (int n = 0; n < 8; n++) {
            uint32_t bh[2], bl[2];
            LDM_X2(bh, bBase + B1H + n * 1152 + kc * 32);
            LDM_X2(bl, bBase + B1L + n * 1152 + kc * 32);
            MMA_BF16(acc[n], ah, bh);
            MMA_BF16(acc[n], ah, bl);
            MMA_BF16(acc[n], al, bh);
        }
    }

    {
        const float* bs = (const float*)(smem + BIAS1);
#pragma unroll
        for (int n = 0; n < 8; n++) {
            int q = n * 8 + 2 * tq;
            float v[4];
            v[0] = acc[n][0] + bs[q];
            v[1] = acc[n][1] + bs[q + 1];
            v[2] = acc[n][2] + bs[q];
            v[3] = acc[n][3] + bs[q + 1];
#pragma unroll
            for (int j = 0; j < 4; j++)
                v[j] = 0.5f * v[j] * (1.0f + erff(v[j] * 0.70710678118654752f));
            uint32_t hi[2], lo[2];
#pragma unroll
            for (int half = 0; half < 2; half++) {
                __nv_bfloat16 h0 = __float2bfloat16(v[2 * half]);
                __nv_bfloat16 h1 = __float2bfloat16(v[2 * half + 1]);
                __nv_bfloat16 l0 = __float2bfloat16(v[2 * half] - __bfloat162float(h0));
                __nv_bfloat16 l1 = __float2bfloat16(v[2 * half + 1] - __bfloat162float(h1));
                hi[half] = ((uint32_t)__bfloat16_as_ushort(h1) << 16) | __bfloat16_as_ushort(h0);
                lo[half] = ((uint32_t)__bfloat16_as_ushort(l1) << 16) | __bfloat16_as_ushort(l0);
            }
            int col = q * 2;
            *(uint32_t*)(smem + AH + r0 * 144 + col) = hi[0];
            *(uint32_t*)(smem + AL + r0 * 144 + col) = lo[0];
            *(uint32_t*)(smem + AH + r1 * 144 + col) = hi[1];
            *(uint32_t*)(smem + AL + r1 * 144 + col) = lo[1];
        }
    }
    __syncwarp();

    // ================= GEMM 2 =================
    float acc2[8][4] = {};
#pragma unroll
    for (int kc = 0; kc < 4; kc++) {
        uint32_t ah[4], al[4];
        LDM_X4(ah, aAdrH + kc * 32);
        LDM_X4(al, aAdrL + kc * 32);
#pragma unroll
        for (int n = 0; n < 8; n++) {
            uint32_t bh[2], bl[2];
            LDM_X2(bh, bBase + B2H + n * 1152 + kc * 32);
            LDM_X2(bl, bBase + B2L + n * 1152 + kc * 32);
            MMA_BF16(acc2[n], ah, bh);
            MMA_BF16(acc2[n], ah, bl);
            MMA_BF16(acc2[n], al, bh);
        }
    }
    __syncthreads();

    {
        const float* bs = (const float*)(smem + BIAS2);
#pragma unroll
        for (int n = 0; n < 8; n++) {
            int q = n * 8 + 2 * tq;
            float2 lo2, hi2;
            lo2.x = acc2[n][0] + bs[q];
            lo2.y = acc2[n][1] + bs[q + 1];
            hi2.x = acc2[n][2] + bs[q];
            hi2.y = acc2[n][3] + bs[q + 1];
            *(float2*)(smem + r0 * 272 + q * 4) = lo2;
            *(float2*)(smem + r1 * 272 + q * 4) = hi2;
        }
    }
    __syncthreads();
    {
        float* dF = outF + ((size_t)c * BDIM + b0) * PDIM;
        const __nv_bfloat16* xht = Ah_g + ((size_t)c * BDIM + b0) * PDIM;  // L1-hot
        const __nv_bfloat16* xlt = Al_g + ((size_t)c * BDIM + b0) * PDIM;
        for (int i = tid; i < 2048; i += 256) {
            int row = i >> 4, ch = i & 15;
            float4 v = *(float4*)(smem + row * 272 + ch * 16);
            uint2 xhp = *(const uint2*)(xht + row * 64 + ch * 4);
            uint2 xlp = *(const uint2*)(xlt + row * 64 + ch * 4);
            v.x += bf16lo(xhp.x) + bf16lo(xlp.x);
            v.y += bf16hi(xhp.x) + bf16hi(xlp.x);
            v.z += bf16lo(xhp.y) + bf16lo(xlp.y);
            v.w += bf16hi(xhp.y) + bf16hi(xlp.y);
            *(float4*)(dF + row * 64 + ch * 4) = v;
        }
    }
}

// ---------------------------------------------------------------------------
// Kernel 4: LayerNorm over channels, 16 rows/CTA, 256 threads, 33.5KB smem.
// Smaller tile -> ~6 CTAs/SM (occupancy was the binder at 32 rows / 64KB).
// ---------------------------------------------------------------------------
#define LNROWS 16
#define LNPAD  524   // 524*4 = 131*16: float4-aligned rows
__global__ void __launch_bounds__(256)
ln_kernel(const float* __restrict__ res,
          const float* __restrict__ gamma, const float* __restrict__ beta,
          float* __restrict__ out)
{
    extern __shared__ float sres[];            // [LNROWS][LNPAD] dynamic
    __shared__ float psum[LNROWS][65], psqs[LNROWS][65];
    __shared__ float pmean[LNROWS], pinv[LNROWS];

    const int b  = blockIdx.y;
    const int q0 = blockIdx.x * LNROWS;
    const int orow0 = b * PDIM + q0;

    const int rg = threadIdx.x & 3;            // row group: rows rg*4..rg*4+3
    const int cg = threadIdx.x >> 2;           // 0..63

    float s[4] = {}, t[4] = {};
#pragma unroll
    for (int it = 0; it < 8; it++) {
        int cc = cg + it * 64;
        float4 v = *(const float4*)(res + (size_t)cc * (BDIM * PDIM) + orow0 + rg * 4);
        sres[(rg * 4 + 0) * LNPAD + cc] = v.x;  s[0] += v.x;  t[0] += v.x * v.x;
        sres[(rg * 4 + 1) * LNPAD + cc] = v.y;  s[1] += v.y;  t[1] += v.y * v.y;
        sres[(rg * 4 + 2) * LNPAD + cc] = v.z;  s[2] += v.z;  t[2] += v.z * v.z;
        sres[(rg * 4 + 3) * LNPAD + cc] = v.w;  s[3] += v.w;  t[3] += v.w * v.w;
    }
#pragma unroll
    for (int j = 0; j < 4; j++) {
        psum[rg * 4 + j][cg] = s[j];
        psqs[rg * 4 + j][cg] = t[j];
    }
    __syncthreads();

    if (threadIdx.x < LNROWS) {
        float S = 0.f, SS = 0.f;
#pragma unroll
        for (int g = 0; g < 64; g++) { S += psum[threadIdx.x][g]; SS += psqs[threadIdx.x][g]; }
        float mean = S * (1.0f / 512.0f);
        float var  = SS * (1.0f / 512.0f) - mean * mean;
        pmean[threadIdx.x] = mean;
        pinv[threadIdx.x]  = rsqrtf(var + 1e-5f);
    }
    __syncthreads();

    const size_t obase = (size_t)orow0 * CDIM;
    for (int i = threadIdx.x; i < LNROWS * 128; i += 256) {
        int q = i >> 7, cw = i & 127;
        float4 v = *(const float4*)(&sres[q * LNPAD + cw * 4]);
        float4 g = *(const float4*)(gamma + cw * 4);
        float4 bt = *(const float4*)(beta + cw * 4);
        float m = pmean[q], inv = pinv[q];
        float4 o4;
        o4.x = (v.x - m) * inv * g.x + bt.x;
        o4.y = (v.y - m) * inv * g.y + bt.y;
        o4.z = (v.z - m) * inv * g.z + bt.z;
        o4.w = (v.w - m) * inv * g.w + bt.w;
        *(float4*)(out + obase + (size_t)q * CDIM + cw * 4) = o4;
    }
}

// ---------------------------------------------------------------------------
extern "C" void kernel_launch(void* const* d_in, const int* in_sizes, int n_in,
                              void* d_out, int out_size)
{
    const float* x     = (const float*)d_in[0];
    const float* W1    = (const float*)d_in[1];
    const float* b1    = (const float*)d_in[2];
    const float* W2    = (const float*)d_in[3];
    const float* b2    = (const float*)d_in[4];
    const float* gamma = (const float*)d_in[5];
    const float* beta  = (const float*)d_in[6];
    float* out = (float*)d_out;

    __nv_bfloat16 *xh, *xl, *w1h, *w1l, *w2h, *w2l;
    float* resbuf;
    cudaGetSymbolAddress((void**)&xh, g_xh);
    cudaGetSymbolAddress((void**)&xl, g_xl);
    cudaGetSymbolAddress((void**)&resbuf, g_res);
    cudaGetSymbolAddress((void**)&w1h, g_w1h);
    cudaGetSymbolAddress((void**)&w1l, g_w1l);
    cudaGetSymbolAddress((void**)&w2h, g_w2h);
    cudaGetSymbolAddress((void**)&w2l, g_w2l);

    const int SMEM_FUSED = 74240;
    const int SMEM_LN = LNROWS * LNPAD * 4;   // 33536 dynamic
    cudaFuncSetAttribute(fused_gemm_kernel, cudaFuncAttributeMaxDynamicSharedMemorySize, SMEM_FUSED);
    cudaFuncSetAttribute(ln_kernel, cudaFuncAttributeMaxDynamicSharedMemorySize, SMEM_LN);

    wsplit_kernel<<<(CDIM * PDIM * PDIM) / (256 * 8), 256>>>(W1, W2, w1h, w1l, w2h, w2l);
    xsplit_kernel<<<dim3(CDIM / 32, BDIM / 4), 256>>>(x, xh, xl);
    fused_gemm_kernel<<<dim3(BDIM / 128, CDIM), 256, SMEM_FUSED>>>(
        xh, xl, w1h, w1l, w2h, w2l, b1, b2, resbuf);
    ln_kernel<<<dim3(PDIM / LNROWS, BDIM), 256, SMEM_LN>>>(resbuf, gamma, beta, out);
}

// round 17
// speedup vs baseline: 1.0478x; 1.0478x over previous
#include <cuda_runtime.h>
#include <cuda_bf16.h>
#include <math.h>
#include <stdint.h>

#define BDIM 1024
#define PDIM 64
#define CDIM 512

// ---------------------------------------------------------------------------
// Scratch (device globals; no allocations allowed)
// ---------------------------------------------------------------------------
__device__ __align__(128) __nv_bfloat16 g_xh[(size_t)CDIM * BDIM * PDIM];
__device__ __align__(128) __nv_bfloat16 g_xl[(size_t)CDIM * BDIM * PDIM];
__device__ __align__(128) float         g_res[(size_t)CDIM * BDIM * PDIM];
__device__ __align__(128) __nv_bfloat16 g_w1h[(size_t)CDIM * PDIM * PDIM];
__device__ __align__(128) __nv_bfloat16 g_w1l[(size_t)CDIM * PDIM * PDIM];
__device__ __align__(128) __nv_bfloat16 g_w2h[(size_t)CDIM * PDIM * PDIM];
__device__ __align__(128) __nv_bfloat16 g_w2l[(size_t)CDIM * PDIM * PDIM];

// ---------------------------------------------------------------------------
// mma.sync / ldmatrix helpers (baseline PTX — compiles for compute_103)
// ---------------------------------------------------------------------------
__device__ __forceinline__ uint32_t smem_u32(const void* p) {
    uint32_t a;
    asm("{ .reg .u64 t; cvta.to.shared.u64 t, %1; cvt.u32.u64 %0, t; }" : "=r"(a) : "l"(p));
    return a;
}

#define LDM_X4(r, addr)                                                         \
    asm volatile("ldmatrix.sync.aligned.m8n8.x4.shared.b16 {%0,%1,%2,%3}, [%4];"\
        : "=r"((r)[0]), "=r"((r)[1]), "=r"((r)[2]), "=r"((r)[3]) : "r"(addr))

#define LDM_X2(r, addr)                                                         \
    asm volatile("ldmatrix.sync.aligned.m8n8.x2.shared.b16 {%0,%1}, [%2];"      \
        : "=r"((r)[0]), "=r"((r)[1]) : "r"(addr))

#define MMA_BF16(c, a, b)                                                       \
    asm volatile("mma.sync.aligned.m16n8k16.row.col.f32.bf16.bf16.f32 "         \
        "{%0,%1,%2,%3}, {%4,%5,%6,%7}, {%8,%9}, {%0,%1,%2,%3};"                 \
        : "+f"((c)[0]), "+f"((c)[1]), "+f"((c)[2]), "+f"((c)[3])                \
        : "r"((a)[0]), "r"((a)[1]), "r"((a)[2]), "r"((a)[3]),                   \
          "r"((b)[0]), "r"((b)[1]))

__device__ __forceinline__ float bf16lo(uint32_t u) { return __uint_as_float(u << 16); }
__device__ __forceinline__ float bf16hi(uint32_t u) { return __uint_as_float(u & 0xFFFF0000u); }

// ---------------------------------------------------------------------------
// Kernel 1: split W -> bf16 hi/lo, 8 elements per thread (vectorized)
// ---------------------------------------------------------------------------
__global__ void __launch_bounds__(256)
wsplit_kernel(const float* __restrict__ W1, const float* __restrict__ W2,
              __nv_bfloat16* __restrict__ w1h, __nv_bfloat16* __restrict__ w1l,
              __nv_bfloat16* __restrict__ w2h, __nv_bfloat16* __restrict__ w2l)
{
    size_t i8 = ((size_t)blockIdx.x * 256 + threadIdx.x) * 8;
#pragma unroll
    for (int w = 0; w < 2; w++) {
        const float* src = w ? W2 : W1;
        __nv_bfloat16* dh = w ? w2h : w1h;
        __nv_bfloat16* dl = w ? w2l : w1l;
        float v[8];
        *(float4*)(v)     = *(const float4*)(src + i8);
        *(float4*)(v + 4) = *(const float4*)(src + i8 + 4);
        __nv_bfloat16 hv[8], lv[8];
#pragma unroll
        for (int j = 0; j < 8; j++) {
            hv[j] = __float2bfloat16(v[j]);
            lv[j] = __float2bfloat16(v[j] - __bfloat162float(hv[j]));
        }
        *(uint4*)(dh + i8) = *(uint4*)hv;
        *(uint4*)(dl + i8) = *(uint4*)lv;
    }
}

// ---------------------------------------------------------------------------
// Kernel 2: transpose + split  x[b,p,c] -> xh/xl[c,b,p] (bf16).
// ---------------------------------------------------------------------------
__global__ void __launch_bounds__(256)
xsplit_kernel(const float* __restrict__ x,
              __nv_bfloat16* __restrict__ xh, __nv_bfloat16* __restrict__ xl)
{
    __shared__ float sm[32][261];
    const int b0 = blockIdx.y * 4;
    const int c0 = blockIdx.x * 32;

    for (int i = threadIdx.x; i < 4 * 64 * 32; i += 256) {
        int cc = i & 31, p = (i >> 5) & 63, b = i >> 11;
        sm[cc][b * 64 + p] = x[((size_t)(b0 + b) * PDIM + p) * CDIM + c0 + cc];
    }
    __syncthreads();

    const int cc = threadIdx.x >> 3;
    const int p0 = (threadIdx.x & 7) * 8;
#pragma unroll
    for (int b = 0; b < 4; b++) {
        __nv_bfloat16 hv[8], lv[8];
#pragma unroll
        for (int i = 0; i < 8; i++) {
            float v = sm[cc][b * 64 + p0 + i];
            hv[i] = __float2bfloat16(v);
            lv[i] = __float2bfloat16(v - __bfloat162float(hv[i]));
        }
        size_t base = ((size_t)(c0 + cc) * BDIM + b0 + b) * PDIM + p0;
        *(uint4*)(xh + base) = *(uint4*)hv;
        *(uint4*)(xl + base) = *(uint4*)lv;
    }
}

// ---------------------------------------------------------------------------
// Kernel 3: FUSED double GEMM per (c, 128-batch tile) [R7 scheme verbatim]
// ---------------------------------------------------------------------------
__global__ void __launch_bounds__(256)
fused_gemm_kernel(const __nv_bfloat16* __restrict__ Ah_g, const __nv_bfloat16* __restrict__ Al_g,
                  const __nv_bfloat16* __restrict__ W1h_g, const __nv_bfloat16* __restrict__ W1l_g,
                  const __nv_bfloat16* __restrict__ W2h_g, const __nv_bfloat16* __restrict__ W2l_g,
                  const float* __restrict__ b1, const float* __restrict__ b2,
                  float* __restrict__ outF)
{
    extern __shared__ __align__(16) char smem[];
    const uint32_t AH = 0, AL = 18432;
    const uint32_t B1H = 36864, B1L = 46080;
    const uint32_t B2H = 55296, B2L = 64512;
    const uint32_t BIAS1 = 73728, BIAS2 = 73984;

    const int tid  = threadIdx.x;
    const int warp = tid >> 5;
    const int lane = tid & 31;
    const int b0   = blockIdx.x * 128;
    const int c    = blockIdx.y;

    {
        const uint4* sAh = (const uint4*)(Ah_g + ((size_t)c * BDIM + b0) * PDIM);
        const uint4* sAl = (const uint4*)(Al_g + ((size_t)c * BDIM + b0) * PDIM);
        for (int i = tid; i < 1024; i += 256) {
            int row = i >> 3, ch = i & 7;
            *(uint4*)(smem + AH + row * 144 + ch * 16) = sAh[i];
            *(uint4*)(smem + AL + row * 144 + ch * 16) = sAl[i];
        }
        const uint4* s1h = (const uint4*)(W1h_g + (size_t)c * PDIM * PDIM);
        const uint4* s1l = (const uint4*)(W1l_g + (size_t)c * PDIM * PDIM);
        const uint4* s2h = (const uint4*)(W2h_g + (size_t)c * PDIM * PDIM);
        const uint4* s2l = (const uint4*)(W2l_g + (size_t)c * PDIM * PDIM);
        for (int i = tid; i < 512; i += 256) {
            int row = i >> 3, ch = i & 7;
            *(uint4*)(smem + B1H + row * 144 + ch * 16) = s1h[i];
            *(uint4*)(smem + B1L + row * 144 + ch * 16) = s1l[i];
            *(uint4*)(smem + B2H + row * 144 + ch * 16) = s2h[i];
            *(uint4*)(smem + B2L + row * 144 + ch * 16) = s2l[i];
        }
        if (tid < 64) {
            ((float*)(smem + BIAS1))[tid] = b1[(size_t)c * PDIM + tid];
            ((float*)(smem + BIAS2))[tid] = b2[(size_t)c * PDIM + tid];
        }
    }
    __syncthreads();

    const uint32_t sb = smem_u32(smem);
    const uint32_t aAdrH = sb + AH + (uint32_t)(warp * 16 + (lane & 15)) * 144 + (uint32_t)(lane >> 4) * 16;
    const uint32_t aAdrL = aAdrH + (AL - AH);
    const uint32_t bBase = sb + (uint32_t)(lane & 7) * 144 + (uint32_t)((lane >> 3) & 1) * 16;

    const int gid = lane >> 2, tq = lane & 3;
    const int r0 = warp * 16 + gid, r1 = r0 + 8;

    // ================= GEMM 1 =================
    float acc[8][4] = {};
#pragma unroll
    for (int kc = 0; kc < 4; kc++) {
        uint32_t ah[4], al[4];
        LDM_X4(ah, aAdrH + kc * 32);
        LDM_X4(al, aAdrL + kc * 32);
#pragma unroll
        for (int n = 0; n < 8; n++) {
            uint32_t bh[2], bl[2];
            LDM_X2(bh, bBase + B1H + n * 1152 + kc * 32);
            LDM_X2(bl, bBase + B1L + n * 1152 + kc * 32);
            MMA_BF16(acc[n], ah, bh);
            MMA_BF16(acc[n], ah, bl);
            MMA_BF16(acc[n], al, bh);
        }
    }

    {
        const float* bs = (const float*)(smem + BIAS1);
#pragma unroll
        for (int n = 0; n < 8; n++) {
            int q = n * 8 + 2 * tq;
            float v[4];
            v[0] = acc[n][0] + bs[q];
            v[1] = acc[n][1] + bs[q + 1];
            v[2] = acc[n][2] + bs[q];
            v[3] = acc[n][3] + bs[q + 1];
#pragma unroll
            for (int j = 0; j < 4; j++)
                v[j] = 0.5f * v[j] * (1.0f + erff(v[j] * 0.70710678118654752f));
            uint32_t hi[2], lo[2];
#pragma unroll
            for (int half = 0; half < 2; half++) {
                __nv_bfloat16 h0 = __float2bfloat16(v[2 * half]);
                __nv_bfloat16 h1 = __float2bfloat16(v[2 * half + 1]);
                __nv_bfloat16 l0 = __float2bfloat16(v[2 * half] - __bfloat162float(h0));
                __nv_bfloat16 l1 = __float2bfloat16(v[2 * half + 1] - __bfloat162float(h1));
                hi[half] = ((uint32_t)__bfloat16_as_ushort(h1) << 16) | __bfloat16_as_ushort(h0);
                lo[half] = ((uint32_t)__bfloat16_as_ushort(l1) << 16) | __bfloat16_as_ushort(l0);
            }
            int col = q * 2;
            *(uint32_t*)(smem + AH + r0 * 144 + col) = hi[0];
            *(uint32_t*)(smem + AL + r0 * 144 + col) = lo[0];
            *(uint32_t*)(smem + AH + r1 * 144 + col) = hi[1];
            *(uint32_t*)(smem + AL + r1 * 144 + col) = lo[1];
        }
    }
    __syncwarp();

    // ================= GEMM 2 =================
    float acc2[8][4] = {};
#pragma unroll
    for (int kc = 0; kc < 4; kc++) {
        uint32_t ah[4], al[4];
        LDM_X4(ah, aAdrH + kc * 32);
        LDM_X4(al, aAdrL + kc * 32);
#pragma unroll
        for (int n = 0; n < 8; n++) {
            uint32_t bh[2], bl[2];
            LDM_X2(bh, bBase + B2H + n * 1152 + kc * 32);
            LDM_X2(bl, bBase + B2L + n * 1152 + kc * 32);
            MMA_BF16(acc2[n], ah, bh);
            MMA_BF16(acc2[n], ah, bl);
            MMA_BF16(acc2[n], al, bh);
        }
    }
    __syncthreads();

    {
        const float* bs = (const float*)(smem + BIAS2);
#pragma unroll
        for (int n = 0; n < 8; n++) {
            int q = n * 8 + 2 * tq;
            float2 lo2, hi2;
            lo2.x = acc2[n][0] + bs[q];
            lo2.y = acc2[n][1] + bs[q + 1];
            hi2.x = acc2[n][2] + bs[q];
            hi2.y = acc2[n][3] + bs[q + 1];
            *(float2*)(smem + r0 * 272 + q * 4) = lo2;
            *(float2*)(smem + r1 * 272 + q * 4) = hi2;
        }
    }
    __syncthreads();
    {
        float* dF = outF + ((size_t)c * BDIM + b0) * PDIM;
        const __nv_bfloat16* xht = Ah_g + ((size_t)c * BDIM + b0) * PDIM;  // L1-hot
        const __nv_bfloat16* xlt = Al_g + ((size_t)c * BDIM + b0) * PDIM;
        for (int i = tid; i < 2048; i += 256) {
            int row = i >> 4, ch = i & 15;
            float4 v = *(float4*)(smem + row * 272 + ch * 16);
            uint2 xhp = *(const uint2*)(xht + row * 64 + ch * 4);
            uint2 xlp = *(const uint2*)(xlt + row * 64 + ch * 4);
            v.x += bf16lo(xhp.x) + bf16lo(xlp.x);
            v.y += bf16hi(xhp.x) + bf16hi(xlp.x);
            v.z += bf16lo(xhp.y) + bf16lo(xlp.y);
            v.w += bf16hi(xhp.y) + bf16hi(xlp.y);
            *(float4*)(dF + row * 64 + ch * 4) = v;
        }
    }
}

// ---------------------------------------------------------------------------
// Kernel 4: LayerNorm over channels.
// 32 rows/CTA (full 128B line per c-slice) + 512 threads (16 warps) +
// conflict-free XOR-swizzled staging (stride 512, key rg<<2) +
// warp-shuffle partial reduction (small static smem -> 3 CTAs/SM).
// ---------------------------------------------------------------------------
#define LNROWS 32
__global__ void __launch_bounds__(512)
ln_kernel(const float* __restrict__ res,
          const float* __restrict__ gamma, const float* __restrict__ beta,
          float* __restrict__ out)
{
    extern __shared__ float sres[];            // [32][512] dynamic, swizzled
    __shared__ float psum[LNROWS][17], psqs[LNROWS][17];
    __shared__ float pmean[LNROWS], pinv[LNROWS];

    const int b  = blockIdx.y;
    const int q0 = blockIdx.x * LNROWS;
    const int orow0 = b * PDIM + q0;

    const int tid  = threadIdx.x;
    const int warp = tid >> 5;
    const int lane = tid & 31;
    const int rg = tid & 7;            // row group: rows rg*4 .. rg*4+3
    const int cg = tid >> 3;           // 0..63
    const int key = rg << 2;           // XOR swizzle key, bits 2-4

    float s[4] = {}, t[4] = {};
#pragma unroll
    for (int it = 0; it < 8; it++) {
        int cc = cg + it * 64;
        float4 v = *(const float4*)(res + (size_t)cc * (BDIM * PDIM) + orow0 + rg * 4);
        int sc = cc ^ key;
        sres[(rg * 4 + 0) * 512 + sc] = v.x;  s[0] += v.x;  t[0] += v.x * v.x;
        sres[(rg * 4 + 1) * 512 + sc] = v.y;  s[1] += v.y;  t[1] += v.y * v.y;
        sres[(rg * 4 + 2) * 512 + sc] = v.z;  s[2] += v.z;  t[2] += v.z * v.z;
        sres[(rg * 4 + 3) * 512 + sc] = v.w;  s[3] += v.w;  t[3] += v.w * v.w;
    }
    // warp reduce across the 4 cg-values sharing each rg (lanes rg, rg+8, rg+16, rg+24)
#pragma unroll
    for (int j = 0; j < 4; j++) {
        s[j] += __shfl_xor_sync(0xffffffffu, s[j], 8);
        t[j] += __shfl_xor_sync(0xffffffffu, t[j], 8);
        s[j] += __shfl_xor_sync(0xffffffffu, s[j], 16);
        t[j] += __shfl_xor_sync(0xffffffffu, t[j], 16);
    }
    if (lane < 8) {
#pragma unroll
        for (int j = 0; j < 4; j++) {
            psum[lane * 4 + j][warp] = s[j];
            psqs[lane * 4 + j][warp] = t[j];
        }
    }
    __syncthreads();

    if (tid < LNROWS) {
        float S = 0.f, SS = 0.f;
#pragma unroll
        for (int g = 0; g < 16; g++) { S += psum[tid][g]; SS += psqs[tid][g]; }
        float mean = S * (1.0f / 512.0f);
        float var  = SS * (1.0f / 512.0f) - mean * mean;
        pmean[tid] = mean;
        pinv[tid]  = rsqrtf(var + 1e-5f);
    }
    __syncthreads();

    const size_t obase = (size_t)orow0 * CDIM;
    for (int i = tid; i < LNROWS * 128; i += 512) {
        int q = i >> 7, cw = i & 127;
        int fsw = (cw * 4) ^ ((q >> 2) << 2);   // same key: rg = q>>2
        float4 v = *(const float4*)(&sres[q * 512 + fsw]);
        float4 g = *(const float4*)(gamma + cw * 4);
        float4 bt = *(const float4*)(beta + cw * 4);
        float m = pmean[q], inv = pinv[q];
        float4 o4;
        o4.x = (v.x - m) * inv * g.x + bt.x;
        o4.y = (v.y - m) * inv * g.y + bt.y;
        o4.z = (v.z - m) * inv * g.z + bt.z;
        o4.w = (v.w - m) * inv * g.w + bt.w;
        *(float4*)(out + obase + (size_t)q * CDIM + cw * 4) = o4;
    }
}

// ---------------------------------------------------------------------------
extern "C" void kernel_launch(void* const* d_in, const int* in_sizes, int n_in,
                              void* d_out, int out_size)
{
    const float* x     = (const float*)d_in[0];
    const float* W1    = (const float*)d_in[1];
    const float* b1    = (const float*)d_in[2];
    const float* W2    = (const float*)d_in[3];
    const float* b2    = (const float*)d_in[4];
    const float* gamma = (const float*)d_in[5];
    const float* beta  = (const float*)d_in[6];
    float* out = (float*)d_out;

    __nv_bfloat16 *xh, *xl, *w1h, *w1l, *w2h, *w2l;
    float* resbuf;
    cudaGetSymbolAddress((void**)&xh, g_xh);
    cudaGetSymbolAddress((void**)&xl, g_xl);
    cudaGetSymbolAddress((void**)&resbuf, g_res);
    cudaGetSymbolAddress((void**)&w1h, g_w1h);
    cudaGetSymbolAddress((void**)&w1l, g_w1l);
    cudaGetSymbolAddress((void**)&w2h, g_w2h);
    cudaGetSymbolAddress((void**)&w2l, g_w2l);

    const int SMEM_FUSED = 74240;
    const int SMEM_LN = LNROWS * 512 * 4;   // 65536 dynamic
    cudaFuncSetAttribute(fused_gemm_kernel, cudaFuncAttributeMaxDynamicSharedMemorySize, SMEM_FUSED);
    cudaFuncSetAttribute(ln_kernel, cudaFuncAttributeMaxDynamicSharedMemorySize, SMEM_LN);

    wsplit_kernel<<<(CDIM * PDIM * PDIM) / (256 * 8), 256>>>(W1, W2, w1h, w1l, w2h, w2l);
    xsplit_kernel<<<dim3(CDIM / 32, BDIM / 4), 256>>>(x, xh, xl);
    fused_gemm_kernel<<<dim3(BDIM / 128, CDIM), 256, SMEM_FUSED>>>(
        xh, xl, w1h, w1l, w2h, w2l, b1, b2, resbuf);
    ln_kernel<<<dim3(PDIM / LNROWS, BDIM), 512, SMEM_LN>>>(resbuf, gamma, beta, out);
}